// round 6
// baseline (speedup 1.0000x reference)
#include <cuda_runtime.h>

#define N_NODES 50000
#define N_EDGES 800000
#define C 64
#define NGRAPH 256

// ---- scratch (static device globals; no allocation allowed) ----
__device__ __align__(16) float g_xws[N_NODES * C];   // dinv-scaled x@W
__device__ __align__(16) float g_h[N_NODES * C];     // layer output
__device__ __align__(16) float g_dinv[N_NODES];
__device__ __align__(16) int   g_deg[N_NODES];
__device__ __align__(16) int   g_rowptr[N_NODES + 1];
__device__ __align__(16) int   g_cursor[N_NODES];
__device__ __align__(16) int   g_col[N_EDGES];
__device__ __align__(16) int   g_gstart[NGRAPH + 1]; // graph segment starts in sorted batch

// ---------------------------------------------------------------
__global__ void k_zero_deg() {
    int i = blockIdx.x * blockDim.x + threadIdx.x;
    if (i < N_NODES) g_deg[i] = 0;
}

__global__ void k_count(const int* __restrict__ dst) {
    int e = blockIdx.x * blockDim.x + threadIdx.x;
    if (e < N_EDGES) atomicAdd(&g_deg[dst[e]], 1);
}

__global__ void k_dinv() {
    int i = blockIdx.x * blockDim.x + threadIdx.x;
    if (i < N_NODES) g_dinv[i] = rsqrtf((float)(g_deg[i] + 1));  // +1 self loop
}

// single-block exclusive scan of g_deg -> g_rowptr / g_cursor
__global__ void k_scan() {
    __shared__ int wsum[32];
    __shared__ int s_carry;
    __shared__ int s_total;
    int tid = threadIdx.x, lane = tid & 31, wid = tid >> 5;
    if (tid == 0) s_carry = 0;
    __syncthreads();
    for (int base = 0; base < N_NODES; base += 1024) {
        int idx = base + tid;
        int val = (idx < N_NODES) ? g_deg[idx] : 0;
        int v = val;
        #pragma unroll
        for (int o = 1; o < 32; o <<= 1) {
            int n = __shfl_up_sync(0xffffffffu, v, o);
            if (lane >= o) v += n;
        }
        if (lane == 31) wsum[wid] = v;
        __syncthreads();
        if (wid == 0) {
            int s = wsum[lane];
            int orig = s;
            #pragma unroll
            for (int o = 1; o < 32; o <<= 1) {
                int n = __shfl_up_sync(0xffffffffu, s, o);
                if (lane >= o) s += n;
            }
            wsum[lane] = s - orig;          // exclusive warp offset
            if (lane == 31) s_total = s;    // block total
        }
        __syncthreads();
        int excl = s_carry + wsum[wid] + v - val;
        if (idx < N_NODES) {
            g_rowptr[idx] = excl;
            g_cursor[idx] = excl;
        }
        __syncthreads();
        if (tid == 0) s_carry += s_total;
        __syncthreads();
    }
    if (tid == 0) g_rowptr[N_NODES] = s_carry;
}

__global__ void k_fill(const int* __restrict__ src,
                       const int* __restrict__ dst) {
    int e = blockIdx.x * blockDim.x + threadIdx.x;
    if (e < N_EDGES) {
        int d = dst[e];
        int pos = atomicAdd(&g_cursor[d], 1);
        g_col[pos] = src[e];
    }
}

// g_gstart[g] = lower_bound(batch, g)  (batch is sorted ascending)
__global__ void k_bounds(const int* __restrict__ batch) {
    int g = blockIdx.x * blockDim.x + threadIdx.x;
    if (g > NGRAPH) return;
    int lo = 0, hi = N_NODES;
    while (lo < hi) {
        int mid = (lo + hi) >> 1;
        if (batch[mid] < g) lo = mid + 1;
        else hi = mid;
    }
    g_gstart[g] = lo;
}

// xws[i][c] = dinv[i] * (in[i] @ W)[c].  in == nullptr -> read g_h.
__global__ void k_gemm_scale(const float* __restrict__ in,
                             const float* __restrict__ W) {
    __shared__ float sW[64 * 64];
    __shared__ float sX[16 * 64];
    const float* src = in ? in : g_h;
    int tid = threadIdx.x;                 // 256 threads
    int block_row = blockIdx.x * 16;
    for (int i = tid; i < 4096; i += 256) sW[i] = W[i];
    for (int i = tid; i < 1024; i += 256) sX[i] = src[block_row * 64 + i];
    __syncthreads();
    int r  = tid >> 4;                     // 0..15 local row
    int c0 = (tid & 15) * 4;               // 4 channels per thread
    float ax = 0.f, ay = 0.f, az = 0.f, aw = 0.f;
    #pragma unroll
    for (int k = 0; k < 64; k++) {
        float xv = sX[r * 64 + k];
        float4 w = *(const float4*)&sW[k * 64 + c0];
        ax += xv * w.x; ay += xv * w.y; az += xv * w.z; aw += xv * w.w;
    }
    float dv = g_dinv[block_row + r];
    float4 o = make_float4(ax * dv, ay * dv, az * dv, aw * dv);
    *(float4*)&g_xws[(block_row + r) * 64 + c0] = o;
}

// h[d] = maybe_relu( dinv[d] * (xws[d] + sum_{s in N(d)} xws[s]) + b )
template <bool RELU>
__global__ void k_gather(const float* __restrict__ b) {
    int node = blockIdx.x * 4 + (threadIdx.x >> 6);
    int c = threadIdx.x & 63;
    if (node >= N_NODES) return;
    float acc0 = g_xws[node * 64 + c];     // self loop term
    float acc1 = 0.f;
    int beg = g_rowptr[node], end = g_rowptr[node + 1];
    int j = beg;
    for (; j + 1 < end; j += 2) {
        int s0 = g_col[j];
        int s1 = g_col[j + 1];
        float v0 = g_xws[s0 * 64 + c];
        float v1 = g_xws[s1 * 64 + c];
        acc0 += v0;
        acc1 += v1;
    }
    if (j < end) acc0 += g_xws[g_col[j] * 64 + c];
    float v = g_dinv[node] * (acc0 + acc1) + b[c];
    if (RELU) v = fmaxf(v, 0.f);
    g_h[node * 64 + c] = v;
}

// global add pool: one block per graph, plain stores to d_out (no atomics).
__global__ void k_pool(float* __restrict__ out) {
    __shared__ float part[256];
    int g = blockIdx.x;
    int tid = threadIdx.x;
    int c = tid & 63;
    int lane = tid >> 6;                    // 0..3
    int beg = g_gstart[g], end = g_gstart[g + 1];
    float acc = 0.f;
    for (int n = beg + lane; n < end; n += 4)
        acc += g_h[n * 64 + c];
    part[tid] = acc;
    __syncthreads();
    if (tid < 64) {
        float v = part[c] + part[c + 64] + part[c + 128] + part[c + 192];
        out[g * 64 + c] = v;               // exactly one writer per element
    }
}

// ---------------------------------------------------------------
extern "C" void kernel_launch(void* const* d_in, const int* in_sizes, int n_in,
                              void* d_out, int out_size) {
    const float* x   = (const float*)d_in[0];
    const int*   ei  = (const int*)d_in[1];     // [2, E] int32 (JAX x64 disabled)
    const int*   bat = (const int*)d_in[2];     // [N] int32, sorted
    const float* W1  = (const float*)d_in[3];
    const float* b1  = (const float*)d_in[4];
    const float* W2  = (const float*)d_in[5];
    const float* b2  = (const float*)d_in[6];
    const float* W3  = (const float*)d_in[7];
    const float* b3  = (const float*)d_in[8];
    float* out = (float*)d_out;

    const int* src = ei;
    const int* dst = ei + N_EDGES;

    // CSR build (per launch; cheap)
    k_zero_deg<<<(N_NODES + 255) / 256, 256>>>();
    k_count<<<(N_EDGES + 255) / 256, 256>>>(dst);
    k_dinv<<<(N_NODES + 255) / 256, 256>>>();
    k_scan<<<1, 1024>>>();
    k_fill<<<(N_EDGES + 255) / 256, 256>>>(src, dst);
    k_bounds<<<2, 256>>>(bat);

    const int gemm_grid   = N_NODES / 16;           // 3125
    const int gather_grid = (N_NODES + 3) / 4;      // 12500

    // layer 1
    k_gemm_scale<<<gemm_grid, 256>>>(x, W1);
    k_gather<true><<<gather_grid, 256>>>(b1);
    // layer 2
    k_gemm_scale<<<gemm_grid, 256>>>(nullptr, W2);
    k_gather<true><<<gather_grid, 256>>>(b2);
    // layer 3
    k_gemm_scale<<<gemm_grid, 256>>>(nullptr, W3);
    k_gather<false><<<gather_grid, 256>>>(b3);

    // pool (no atomics on d_out)
    k_pool<<<NGRAPH, 256>>>(out);
}

// round 7
// speedup vs baseline: 1.1431x; 1.1431x over previous
#include <cuda_runtime.h>

#define N_NODES 50000
#define N_EDGES 800000
#define C 64
#define NGRAPH 256

#define SCAN_ELEMS 2048
#define SCAN_GRID ((N_NODES + SCAN_ELEMS - 1) / SCAN_ELEMS)   // 25

// ---- scratch (static device globals; no allocation allowed) ----
__device__ __align__(16) float g_xws[N_NODES * C];   // dinv-scaled x@W
__device__ __align__(16) float g_h[N_NODES * C];     // layer output
__device__ __align__(16) float g_dinv[N_NODES];
__device__ __align__(16) int   g_deg[N_NODES];
__device__ __align__(16) int   g_rowptr[N_NODES + 1];
__device__ __align__(16) int   g_cursor[N_NODES];
__device__ __align__(16) int   g_col[N_EDGES];
__device__ __align__(16) int   g_gstart[NGRAPH + 1];
__device__ __align__(16) int   g_bsum[SCAN_GRID];

// ---------------------------------------------------------------
__global__ void k_zero_deg() {
    int i = blockIdx.x * blockDim.x + threadIdx.x;
    if (i < N_NODES) g_deg[i] = 0;
}

__global__ void k_count(const int* __restrict__ dst) {
    int e = blockIdx.x * blockDim.x + threadIdx.x;
    if (e < N_EDGES) atomicAdd(&g_deg[dst[e]], 1);
}

// ---- multi-block exclusive scan of g_deg ----
// Phase A: per-block (2048 elems) local exclusive scan + block sums
__global__ void k_scanA() {
    __shared__ int wsum[32];
    __shared__ int s_total;
    int tid = threadIdx.x, lane = tid & 31, wid = tid >> 5;
    int base = blockIdx.x * SCAN_ELEMS;
    int i0 = base + 2 * tid, i1 = i0 + 1;
    int v0 = (i0 < N_NODES) ? g_deg[i0] : 0;
    int v1 = (i1 < N_NODES) ? g_deg[i1] : 0;
    int pair = v0 + v1;
    int v = pair;
    #pragma unroll
    for (int o = 1; o < 32; o <<= 1) {
        int n = __shfl_up_sync(0xffffffffu, v, o);
        if (lane >= o) v += n;
    }
    if (lane == 31) wsum[wid] = v;
    __syncthreads();
    if (wid == 0) {
        int s = wsum[lane];
        int orig = s;
        #pragma unroll
        for (int o = 1; o < 32; o <<= 1) {
            int n = __shfl_up_sync(0xffffffffu, s, o);
            if (lane >= o) s += n;
        }
        wsum[lane] = s - orig;            // exclusive warp offsets
        if (lane == 31) s_total = s;      // block total
    }
    __syncthreads();
    int excl = wsum[wid] + v - pair;      // exclusive prefix for this pair
    if (i0 < N_NODES) g_rowptr[i0] = excl;
    if (i1 < N_NODES) g_rowptr[i1] = excl + v0;
    if (tid == 0) g_bsum[blockIdx.x] = s_total;
}

// Phase B: scan the 25 block sums (one warp); write grand total to rowptr[N]
__global__ void k_scanB() {
    int lane = threadIdx.x;               // 32 threads
    int v = (lane < SCAN_GRID) ? g_bsum[lane] : 0;
    int s = v;
    #pragma unroll
    for (int o = 1; o < 32; o <<= 1) {
        int n = __shfl_up_sync(0xffffffffu, s, o);
        if (lane >= o) s += n;
    }
    if (lane < SCAN_GRID) g_bsum[lane] = s - v;   // exclusive
    if (lane == 31) g_rowptr[N_NODES] = s;        // total (= E since all lanes≥grid add 0)
}

// Phase C: add block offsets, init cursor, and fused dinv
__global__ void k_scanC() {
    int i = blockIdx.x * blockDim.x + threadIdx.x;
    if (i < N_NODES) {
        int r = g_rowptr[i] + g_bsum[i / SCAN_ELEMS];
        g_rowptr[i] = r;
        g_cursor[i] = r;
        g_dinv[i] = rsqrtf((float)(g_deg[i] + 1));   // +1 self loop
    }
}

__global__ void k_fill(const int* __restrict__ src,
                       const int* __restrict__ dst) {
    int e = blockIdx.x * blockDim.x + threadIdx.x;
    if (e < N_EDGES) {
        int d = dst[e];
        int pos = atomicAdd(&g_cursor[d], 1);
        g_col[pos] = src[e];
    }
}

// g_gstart[g] = lower_bound(batch, g)  (batch is sorted ascending)
__global__ void k_bounds(const int* __restrict__ batch) {
    int g = blockIdx.x * blockDim.x + threadIdx.x;
    if (g > NGRAPH) return;
    int lo = 0, hi = N_NODES;
    while (lo < hi) {
        int mid = (lo + hi) >> 1;
        if (batch[mid] < g) lo = mid + 1;
        else hi = mid;
    }
    g_gstart[g] = lo;
}

// xws[i][c] = dinv[i] * (in[i] @ W)[c].  in == nullptr -> read g_h.
__global__ void k_gemm_scale(const float* __restrict__ in,
                             const float* __restrict__ W) {
    __shared__ float sW[64 * 64];
    __shared__ float sX[16 * 64];
    const float* src = in ? in : g_h;
    int tid = threadIdx.x;                 // 256 threads
    int block_row = blockIdx.x * 16;
    for (int i = tid; i < 4096; i += 256) sW[i] = W[i];
    for (int i = tid; i < 1024; i += 256) sX[i] = src[block_row * 64 + i];
    __syncthreads();
    int r  = tid >> 4;                     // 0..15 local row
    int c0 = (tid & 15) * 4;               // 4 channels per thread
    float ax = 0.f, ay = 0.f, az = 0.f, aw = 0.f;
    #pragma unroll
    for (int k = 0; k < 64; k++) {
        float xv = sX[r * 64 + k];
        float4 w = *(const float4*)&sW[k * 64 + c0];
        ax += xv * w.x; ay += xv * w.y; az += xv * w.z; aw += xv * w.w;
    }
    float dv = g_dinv[block_row + r];
    float4 o = make_float4(ax * dv, ay * dv, az * dv, aw * dv);
    *(float4*)&g_xws[(block_row + r) * 64 + c0] = o;
}

// h[d] = maybe_relu( dinv[d] * (xws[d] + sum_{s in N(d)} xws[s]) + b )
template <bool RELU>
__global__ void k_gather(const float* __restrict__ b) {
    int node = blockIdx.x * 4 + (threadIdx.x >> 6);
    int c = threadIdx.x & 63;
    if (node >= N_NODES) return;
    float acc0 = g_xws[node * 64 + c];     // self loop term
    float acc1 = 0.f;
    int beg = g_rowptr[node], end = g_rowptr[node + 1];
    int j = beg;
    for (; j + 1 < end; j += 2) {
        int s0 = g_col[j];
        int s1 = g_col[j + 1];
        float v0 = g_xws[s0 * 64 + c];
        float v1 = g_xws[s1 * 64 + c];
        acc0 += v0;
        acc1 += v1;
    }
    if (j < end) acc0 += g_xws[g_col[j] * 64 + c];
    float v = g_dinv[node] * (acc0 + acc1) + b[c];
    if (RELU) v = fmaxf(v, 0.f);
    g_h[node * 64 + c] = v;
}

// global add pool: one block per graph, plain stores to d_out (no atomics).
__global__ void k_pool(float* __restrict__ out) {
    __shared__ float part[256];
    int g = blockIdx.x;
    int tid = threadIdx.x;
    int c = tid & 63;
    int lane = tid >> 6;                    // 0..3
    int beg = g_gstart[g], end = g_gstart[g + 1];
    float acc = 0.f;
    for (int n = beg + lane; n < end; n += 4)
        acc += g_h[n * 64 + c];
    part[tid] = acc;
    __syncthreads();
    if (tid < 64) {
        float v = part[c] + part[c + 64] + part[c + 128] + part[c + 192];
        out[g * 64 + c] = v;               // exactly one writer per element
    }
}

// ---------------------------------------------------------------
extern "C" void kernel_launch(void* const* d_in, const int* in_sizes, int n_in,
                              void* d_out, int out_size) {
    const float* x   = (const float*)d_in[0];
    const int*   ei  = (const int*)d_in[1];     // [2, E] int32
    const int*   bat = (const int*)d_in[2];     // [N] int32, sorted
    const float* W1  = (const float*)d_in[3];
    const float* b1  = (const float*)d_in[4];
    const float* W2  = (const float*)d_in[5];
    const float* b2  = (const float*)d_in[6];
    const float* W3  = (const float*)d_in[7];
    const float* b3  = (const float*)d_in[8];
    float* out = (float*)d_out;

    const int* src = ei;
    const int* dst = ei + N_EDGES;

    // CSR build (per launch)
    k_zero_deg<<<(N_NODES + 255) / 256, 256>>>();
    k_count<<<(N_EDGES + 255) / 256, 256>>>(dst);
    k_scanA<<<SCAN_GRID, 1024>>>();
    k_scanB<<<1, 32>>>();
    k_scanC<<<(N_NODES + 255) / 256, 256>>>();
    k_fill<<<(N_EDGES + 255) / 256, 256>>>(src, dst);
    k_bounds<<<2, 256>>>(bat);

    const int gemm_grid   = N_NODES / 16;           // 3125
    const int gather_grid = (N_NODES + 3) / 4;      // 12500

    // layer 1
    k_gemm_scale<<<gemm_grid, 256>>>(x, W1);
    k_gather<true><<<gather_grid, 256>>>(b1);
    // layer 2
    k_gemm_scale<<<gemm_grid, 256>>>(nullptr, W2);
    k_gather<true><<<gather_grid, 256>>>(b2);
    // layer 3
    k_gemm_scale<<<gemm_grid, 256>>>(nullptr, W3);
    k_gather<false><<<gather_grid, 256>>>(b3);

    // pool (no atomics on d_out)
    k_pool<<<NGRAPH, 256>>>(out);
}